// round 14
// baseline (speedup 1.0000x reference)
#include <cuda_runtime.h>
#include <cuda_fp16.h>
#include <cstdint>

// CantorAttention: B=2, S=2048, DIM=1024, H=16, HD=64, K=64
// GEMMs via mma.sync fp16, 2-product split: C = (Ah+Al) @ Bh^T.
// Attention: fused single pass, 4 groups x 8 lanes, per-lane-src route shfl.

#define BB   2
#define SS   2048
#define DIM  1024
#define HH   16
#define HD   64
#define KK   64
#define MM   (BB * SS)        // 4096
#define KD   1024

// ---------------- scratch ---------------------------------------------------
static __device__ float g_qkv[(size_t)MM * 3 * DIM];
static __device__ __half g_xh[(size_t)MM * KD],  g_xl[(size_t)MM * KD];
static __device__ __half g_wqh[(size_t)3 * DIM * KD];
static __device__ __half g_ah[(size_t)MM * KD],  g_al[(size_t)MM * KD];
static __device__ __half g_woh[(size_t)DIM * KD];

// ---------------- helpers ---------------------------------------------------
__device__ __forceinline__ uint32_t smem_u32(const void* p) {
    uint32_t a;
    asm("{ .reg .u64 t; cvta.to.shared.u64 t, %1; cvt.u32.u64 %0, t; }" : "=r"(a) : "l"(p));
    return a;
}
#define CP_ASYNC16(d, s)  asm volatile("cp.async.cg.shared.global [%0], [%1], 16;" :: "r"(d), "l"(s) : "memory")
#define CP_COMMIT()       asm volatile("cp.async.commit_group;" ::: "memory")
#define CP_WAIT(n)        asm volatile("cp.async.wait_group %0;" :: "n"(n) : "memory")

__device__ __forceinline__ void ldsm_x4(uint32_t* r, uint32_t addr) {
    asm volatile("ldmatrix.sync.aligned.m8n8.x4.shared.b16 {%0,%1,%2,%3}, [%4];"
                 : "=r"(r[0]), "=r"(r[1]), "=r"(r[2]), "=r"(r[3]) : "r"(addr));
}
__device__ __forceinline__ void mma_f16(float* d, const uint32_t* a, const uint32_t* b) {
    asm volatile("mma.sync.aligned.m16n8k16.row.col.f32.f16.f16.f32 "
                 "{%0,%1,%2,%3}, {%4,%5,%6,%7}, {%8,%9}, {%0,%1,%2,%3};"
                 : "+f"(d[0]), "+f"(d[1]), "+f"(d[2]), "+f"(d[3])
                 : "r"(a[0]), "r"(a[1]), "r"(a[2]), "r"(a[3]), "r"(b[0]), "r"(b[1]));
}

// ---------------- fused split: x->(hi,lo), w_qkv->hi, w_out->hi --------------
#define N4_X   (MM * KD / 4)              // 1048576
#define N4_WQ  (3 * DIM * KD / 4)         // 786432
#define N4_WO  (DIM * KD / 4)             // 262144
#define N4_ALL (N4_X + N4_WQ + N4_WO)

__global__ __launch_bounds__(256)
void split_all(const float* __restrict__ x, const float* __restrict__ wq,
               const float* __restrict__ wo)
{
    int i = blockIdx.x * 256 + threadIdx.x;
    if (i < N4_X) {
        float4 a = ((const float4*)x)[i];
        __half h0 = __float2half_rn(a.x), h1 = __float2half_rn(a.y);
        __half h2 = __float2half_rn(a.z), h3 = __float2half_rn(a.w);
        __half2* H = (__half2*)g_xh;
        __half2* L = (__half2*)g_xl;
        H[i * 2 + 0] = __half2(h0, h1);
        H[i * 2 + 1] = __half2(h2, h3);
        L[i * 2 + 0] = __half2(__float2half_rn(a.x - __half2float(h0)),
                               __float2half_rn(a.y - __half2float(h1)));
        L[i * 2 + 1] = __half2(__float2half_rn(a.z - __half2float(h2)),
                               __float2half_rn(a.w - __half2float(h3)));
    } else if (i < N4_X + N4_WQ) {
        int j = i - N4_X;
        float4 a = ((const float4*)wq)[j];
        __half2* H = (__half2*)g_wqh;
        H[j * 2 + 0] = __half2(__float2half_rn(a.x), __float2half_rn(a.y));
        H[j * 2 + 1] = __half2(__float2half_rn(a.z), __float2half_rn(a.w));
    } else if (i < N4_ALL) {
        int j = i - N4_X - N4_WQ;
        float4 a = ((const float4*)wo)[j];
        __half2* H = (__half2*)g_woh;
        H[j * 2 + 0] = __half2(__float2half_rn(a.x), __float2half_rn(a.y));
        H[j * 2 + 1] = __half2(__float2half_rn(a.z), __float2half_rn(a.w));
    }
}

// ---------------- mma.sync GEMM: C[M,N] = (Ah+Al) @ Bh^T + bias -------------
// 128x128 block, BK=128 (two 64-col subtiles, SW128), 8 warps (64x32 warp
// tile), 2-stage double buffer, ping-pong ldmatrix fragments.
#define SUB_B   16384
#define OP_B    32768
#define STAGE_B (3 * OP_B)             // Ah, Al, Bh  (96 KB)
#define NCH     (KD / 128)             // 8 chunks

__device__ __forceinline__ uint32_t swz(int row, int u) {
    return (uint32_t)(row * 128 + ((u ^ (row & 7)) << 4));
}

__device__ __forceinline__ void load_stage(
    uint32_t sbase, int s, int chunk, int tm0, int tn0,
    const __half* Ah, const __half* Al, const __half* Bh, int tid)
{
    const __half* srcs[3] = {Ah, Al, Bh};
    uint32_t st = sbase + s * STAGE_B;
#pragma unroll
    for (int i = 0; i < 24; i++) {
        int id  = tid + (i << 8);
        int t   = id >> 11;
        int rem = id & 2047;
        int sub = rem >> 10;
        int rr  = rem & 1023;
        int row = rr >> 3;
        int u   = rr & 7;
        int g0  = (t < 2) ? tm0 : tn0;
        const __half* src = srcs[t] + (size_t)(g0 + row) * KD + chunk * 128 + sub * 64 + u * 8;
        CP_ASYNC16(st + t * OP_B + sub * SUB_B + swz(row, u), src);
    }
    CP_COMMIT();
}

struct Frag {
    uint32_t a_h[4][4], a_l[4][4];
    uint32_t b_h[4][2];
};

__device__ __forceinline__ void load_frags(Frag& f, uint32_t st, int ks,
                                           int wm, int wn, int lane)
{
    const uint32_t sb = st + (uint32_t)((ks >> 2) * SUB_B);
    const int ksl = ks & 3;
    const int ar = lane & 15;
    const int au = ksl * 2 + (lane >> 4);
#pragma unroll
    for (int mt = 0; mt < 4; mt++) {
        uint32_t off = swz(wm + mt * 16 + ar, au);
        ldsm_x4(f.a_h[mt], sb + 0 * OP_B + off);
        ldsm_x4(f.a_l[mt], sb + 1 * OP_B + off);
    }
    const int br = lane & 7;
    const int bu = ksl * 2 + ((lane >> 3) & 1);
    const int bt = (lane >> 4) & 1;
#pragma unroll
    for (int p = 0; p < 2; p++) {
        uint32_t off = swz(wn + (p * 2 + bt) * 8 + br, bu);
        ldsm_x4(&f.b_h[p * 2][0], sb + 2 * OP_B + off);
    }
}

__device__ __forceinline__ void mma_all(float (*acc)[4][4], const Frag& f)
{
#pragma unroll
    for (int mt = 0; mt < 4; mt++)
#pragma unroll
        for (int nt = 0; nt < 4; nt++)
            mma_f16(acc[mt][nt], f.a_h[mt], f.b_h[nt]);
#pragma unroll
    for (int mt = 0; mt < 4; mt++)
#pragma unroll
        for (int nt = 0; nt < 4; nt++)
            mma_f16(acc[mt][nt], f.a_l[mt], f.b_h[nt]);
}

__global__ __launch_bounds__(256, 1)
void gemm_mma(const __half* __restrict__ Ah, const __half* __restrict__ Al,
              const __half* __restrict__ Bh,
              const float* __restrict__ bias, float* __restrict__ C, int N)
{
    extern __shared__ __align__(128) char smem[];
    const uint32_t sbase = smem_u32(smem);
    const int tid = threadIdx.x, wid = tid >> 5, lane = tid & 31;
    const int tn0 = blockIdx.x * 128, tm0 = blockIdx.y * 128;
    const int wm = (wid & 1) * 64;
    const int wn = (wid >> 1) * 32;

    float acc[4][4][4];
#pragma unroll
    for (int i = 0; i < 4; i++)
#pragma unroll
        for (int j = 0; j < 4; j++)
#pragma unroll
            for (int k = 0; k < 4; k++) acc[i][j][k] = 0.0f;

    Frag f0, f1;
    load_stage(sbase, 0, 0, tm0, tn0, Ah, Al, Bh, tid);

    for (int c = 0; c < NCH; c++) {
        CP_WAIT(0);
        __syncthreads();
        if (c + 1 < NCH)
            load_stage(sbase, (c + 1) & 1, c + 1, tm0, tn0, Ah, Al, Bh, tid);

        const uint32_t st = sbase + (c & 1) * STAGE_B;
        load_frags(f0, st, 0, wm, wn, lane);
        load_frags(f1, st, 1, wm, wn, lane);
#pragma unroll
        for (int ks = 0; ks < 6; ks += 2) {
            mma_all(acc, f0);
            load_frags(f0, st, ks + 2, wm, wn, lane);
            mma_all(acc, f1);
            load_frags(f1, st, ks + 3, wm, wn, lane);
        }
        mma_all(acc, f0);
        mma_all(acc, f1);
        __syncthreads();
    }

    const int erow = tm0 + wm + (lane >> 2);
    const int ecol = tn0 + wn + (lane & 3) * 2;
#pragma unroll
    for (int mt = 0; mt < 4; mt++) {
#pragma unroll
        for (int nt = 0; nt < 4; nt++) {
            int col = ecol + nt * 8;
            float b0 = bias[col], b1 = bias[col + 1];
            float* p0 = C + (size_t)(erow + mt * 16) * N + col;
            float* p1 = C + (size_t)(erow + mt * 16 + 8) * N + col;
            *(float2*)p0 = make_float2(acc[mt][nt][0] + b0, acc[mt][nt][1] + b1);
            *(float2*)p1 = make_float2(acc[mt][nt][2] + b0, acc[mt][nt][3] + b1);
        }
    }
}

// ---------------- gathered attention: 4 groups x 8 lanes --------------------
// Warp = one query. Group g=lane>>3 handles neighbor n=4i+g (16 iterations);
// sub=lane&7 owns dims 8*sub..+7 (two float4 per row). One route SHFL per
// iteration (per-lane source index serves all 4 groups), 3-deep butterfly,
// exp count halved vs 2-group scheme. Final 2-shfl cross-group combine.
// Group 0 writes fp16-hi, group 1 writes fp16-lo (fused split for GEMM2).
__global__ __launch_bounds__(512)
void attn_kernel(const int* __restrict__ routes)
{
    const unsigned FULL = 0xffffffffu;
    const int lane = threadIdx.x & 31;
    const int warp = threadIdx.x >> 5;
    const int g    = lane >> 3;          // 0..3
    const int sub  = lane & 7;           // owns dims 8*sub..+7
    const int bh = blockIdx.x >> 7;      // 128 blocks per (b,h)
    const int q  = ((blockIdx.x & 127) << 4) | warp;
    const int b  = bh >> 4;
    const int h  = bh & 15;

    const float* qkv = g_qkv;
    const size_t bbase = (size_t)b * SS * 3 * DIM;
    const float* kbase = qkv + bbase + DIM + h * HD;
    const float* vbase = qkv + bbase + 2 * DIM + h * HD;

    const float* qrow = qkv + bbase + (size_t)q * 3 * DIM + h * HD + 8 * sub;
    const float4 qv0 = *(const float4*)(qrow);
    const float4 qv1 = *(const float4*)(qrow + 4);

    const int* rt = routes + q * KK;
    const int r_lo = rt[lane];
    const int r_hi = rt[lane + 32];

    float s = 0.0f;
    float o0 = 0.0f, o1 = 0.0f, o2 = 0.0f, o3 = 0.0f;
    float o4 = 0.0f, o5 = 0.0f, o6 = 0.0f, o7 = 0.0f;

#pragma unroll
    for (int i = 0; i < 16; i++) {
        const int src = (4 * i + g) & 31;     // neighbor n = 4i+g
        const int r = __shfl_sync(FULL, (i < 8) ? r_lo : r_hi, src);
        const size_t roff = (size_t)r * 3 * DIM + 8 * sub;
        const float4 k0 = *(const float4*)(kbase + roff);
        const float4 k1 = *(const float4*)(kbase + roff + 4);
        const float4 v0 = *(const float4*)(vbase + roff);
        const float4 v1 = *(const float4*)(vbase + roff + 4);
        float p = qv0.x * k0.x + qv0.y * k0.y + qv0.z * k0.z + qv0.w * k0.w
                + qv1.x * k1.x + qv1.y * k1.y + qv1.z * k1.z + qv1.w * k1.w;
        p += __shfl_xor_sync(FULL, p, 4);
        p += __shfl_xor_sync(FULL, p, 2);
        p += __shfl_xor_sync(FULL, p, 1);
        const float e = __expf(p * 0.125f);
        s += e;
        o0 = fmaf(e, v0.x, o0); o1 = fmaf(e, v0.y, o1);
        o2 = fmaf(e, v0.z, o2); o3 = fmaf(e, v0.w, o3);
        o4 = fmaf(e, v1.x, o4); o5 = fmaf(e, v1.y, o5);
        o6 = fmaf(e, v1.z, o6); o7 = fmaf(e, v1.w, o7);
    }

    // combine the 4 groups (lanes sharing `sub`)
    s  += __shfl_xor_sync(FULL, s, 8);   s  += __shfl_xor_sync(FULL, s, 16);
    o0 += __shfl_xor_sync(FULL, o0, 8);  o0 += __shfl_xor_sync(FULL, o0, 16);
    o1 += __shfl_xor_sync(FULL, o1, 8);  o1 += __shfl_xor_sync(FULL, o1, 16);
    o2 += __shfl_xor_sync(FULL, o2, 8);  o2 += __shfl_xor_sync(FULL, o2, 16);
    o3 += __shfl_xor_sync(FULL, o3, 8);  o3 += __shfl_xor_sync(FULL, o3, 16);
    o4 += __shfl_xor_sync(FULL, o4, 8);  o4 += __shfl_xor_sync(FULL, o4, 16);
    o5 += __shfl_xor_sync(FULL, o5, 8);  o5 += __shfl_xor_sync(FULL, o5, 16);
    o6 += __shfl_xor_sync(FULL, o6, 8);  o6 += __shfl_xor_sync(FULL, o6, 16);
    o7 += __shfl_xor_sync(FULL, o7, 8);  o7 += __shfl_xor_sync(FULL, o7, 16);

    const float inv = 1.0f / s;
    o0 *= inv; o1 *= inv; o2 *= inv; o3 *= inv;
    o4 *= inv; o5 *= inv; o6 *= inv; o7 *= inv;

    // fused fp16 hi/lo split: group 0 -> g_ah, group 1 -> g_al (16B stores)
    const size_t obase = (size_t)(b * SS + q) * DIM + h * HD + 8 * sub;
    __half h0 = __float2half_rn(o0), h1 = __float2half_rn(o1);
    __half h2 = __float2half_rn(o2), h3 = __float2half_rn(o3);
    __half h4 = __float2half_rn(o4), h5 = __float2half_rn(o5);
    __half h6 = __float2half_rn(o6), h7 = __float2half_rn(o7);
    if (g == 0) {
        __half2 p0(h0, h1), p1(h2, h3), p2(h4, h5), p3(h6, h7);
        uint4 pk;
        pk.x = *(uint32_t*)&p0; pk.y = *(uint32_t*)&p1;
        pk.z = *(uint32_t*)&p2; pk.w = *(uint32_t*)&p3;
        *(uint4*)(g_ah + obase) = pk;
    } else if (g == 1) {
        __half2 p0(__float2half_rn(o0 - __half2float(h0)),
                   __float2half_rn(o1 - __half2float(h1)));
        __half2 p1(__float2half_rn(o2 - __half2float(h2)),
                   __float2half_rn(o3 - __half2float(h3)));
        __half2 p2(__float2half_rn(o4 - __half2float(h4)),
                   __float2half_rn(o5 - __half2float(h5)));
        __half2 p3(__float2half_rn(o6 - __half2float(h6)),
                   __float2half_rn(o7 - __half2float(h7)));
        uint4 pk;
        pk.x = *(uint32_t*)&p0; pk.y = *(uint32_t*)&p1;
        pk.z = *(uint32_t*)&p2; pk.w = *(uint32_t*)&p3;
        *(uint4*)(g_al + obase) = pk;
    }
}

// ---------------------------------------------------------------------------
extern "C" void kernel_launch(void* const* d_in, const int* in_sizes, int n_in,
                              void* d_out, int out_size)
{
    const float* x     = (const float*)d_in[0];
    const float* w_qkv = (const float*)d_in[1];
    const float* b_qkv = (const float*)d_in[2];
    const float* w_out = (const float*)d_in[3];
    const float* b_out = (const float*)d_in[4];
    const int*   routes= (const int*)  d_in[5];
    float* out = (float*)d_out;

    float* qkv;
    __half *xh, *xl, *wqh, *ah, *al, *woh;
    cudaGetSymbolAddress((void**)&qkv,  g_qkv);
    cudaGetSymbolAddress((void**)&xh,  g_xh);  cudaGetSymbolAddress((void**)&xl,  g_xl);
    cudaGetSymbolAddress((void**)&wqh, g_wqh);
    cudaGetSymbolAddress((void**)&ah,  g_ah);  cudaGetSymbolAddress((void**)&al,  g_al);
    cudaGetSymbolAddress((void**)&woh, g_woh);

    const int SMEM_TOTAL = 2 * STAGE_B;   // 192 KB
    cudaFuncSetAttribute(gemm_mma, cudaFuncAttributeMaxDynamicSharedMemorySize, SMEM_TOTAL);

    // fused input splits (one launch)
    split_all<<<(N4_ALL + 255) / 256, 256>>>(x, w_qkv, w_out);

    // 1) qkv = x @ w_qkv^T + b_qkv : [4096, 3072]
    {
        dim3 grid((3 * DIM) / 128, MM / 128);
        gemm_mma<<<grid, 256, SMEM_TOTAL>>>(xh, xl, wqh, b_qkv, qkv, 3 * DIM);
    }

    // 2) gathered attention (writes fp16 hi/lo directly)
    {
        dim3 grid(BB * HH * (SS / 16));
        attn_kernel<<<grid, 512>>>(routes);
    }

    // 3) out = attn @ w_out^T + b_out : [4096, 1024]
    {
        dim3 grid(DIM / 128, MM / 128);
        gemm_mma<<<grid, 256, SMEM_TOTAL>>>(ah, al, woh, b_out, out, DIM);
    }
}

// round 15
// speedup vs baseline: 1.1514x; 1.1514x over previous
#include <cuda_runtime.h>
#include <cuda_fp16.h>
#include <cstdint>

// CantorAttention: B=2, S=2048, DIM=1024, H=16, HD=64, K=64
// GEMMs via mma.sync fp16, 2-product split: C = (Ah+Al) @ Bh^T.
// GEMM1 epilogue writes Q fp32, K/V fp16 (halves attention traffic).
// Attention: round-13 2-group scheme, fp16 K/V loads, fused output split.

#define BB   2
#define SS   2048
#define DIM  1024
#define HH   16
#define HD   64
#define KK   64
#define MM   (BB * SS)        // 4096
#define KD   1024

// ---------------- scratch ---------------------------------------------------
static __device__ float  g_qf[(size_t)MM * DIM];            // Q fp32
static __device__ __half g_k16[(size_t)MM * DIM];           // K fp16
static __device__ __half g_v16[(size_t)MM * DIM];           // V fp16
static __device__ __half g_xh[(size_t)MM * KD],  g_xl[(size_t)MM * KD];
static __device__ __half g_wqh[(size_t)3 * DIM * KD];
static __device__ __half g_ah[(size_t)MM * KD],  g_al[(size_t)MM * KD];
static __device__ __half g_woh[(size_t)DIM * KD];

// ---------------- helpers ---------------------------------------------------
__device__ __forceinline__ uint32_t smem_u32(const void* p) {
    uint32_t a;
    asm("{ .reg .u64 t; cvta.to.shared.u64 t, %1; cvt.u32.u64 %0, t; }" : "=r"(a) : "l"(p));
    return a;
}
#define CP_ASYNC16(d, s)  asm volatile("cp.async.cg.shared.global [%0], [%1], 16;" :: "r"(d), "l"(s) : "memory")
#define CP_COMMIT()       asm volatile("cp.async.commit_group;" ::: "memory")
#define CP_WAIT(n)        asm volatile("cp.async.wait_group %0;" :: "n"(n) : "memory")

__device__ __forceinline__ void ldsm_x4(uint32_t* r, uint32_t addr) {
    asm volatile("ldmatrix.sync.aligned.m8n8.x4.shared.b16 {%0,%1,%2,%3}, [%4];"
                 : "=r"(r[0]), "=r"(r[1]), "=r"(r[2]), "=r"(r[3]) : "r"(addr));
}
__device__ __forceinline__ void mma_f16(float* d, const uint32_t* a, const uint32_t* b) {
    asm volatile("mma.sync.aligned.m16n8k16.row.col.f32.f16.f16.f32 "
                 "{%0,%1,%2,%3}, {%4,%5,%6,%7}, {%8,%9}, {%0,%1,%2,%3};"
                 : "+f"(d[0]), "+f"(d[1]), "+f"(d[2]), "+f"(d[3])
                 : "r"(a[0]), "r"(a[1]), "r"(a[2]), "r"(a[3]), "r"(b[0]), "r"(b[1]));
}

// ---------------- fused split: x->(hi,lo), w_qkv->hi, w_out->hi --------------
#define N4_X   (MM * KD / 4)
#define N4_WQ  (3 * DIM * KD / 4)
#define N4_WO  (DIM * KD / 4)
#define N4_ALL (N4_X + N4_WQ + N4_WO)

__global__ __launch_bounds__(256)
void split_all(const float* __restrict__ x, const float* __restrict__ wq,
               const float* __restrict__ wo)
{
    int i = blockIdx.x * 256 + threadIdx.x;
    if (i < N4_X) {
        float4 a = ((const float4*)x)[i];
        __half h0 = __float2half_rn(a.x), h1 = __float2half_rn(a.y);
        __half h2 = __float2half_rn(a.z), h3 = __float2half_rn(a.w);
        __half2* H = (__half2*)g_xh;
        __half2* L = (__half2*)g_xl;
        H[i * 2 + 0] = __half2(h0, h1);
        H[i * 2 + 1] = __half2(h2, h3);
        L[i * 2 + 0] = __half2(__float2half_rn(a.x - __half2float(h0)),
                               __float2half_rn(a.y - __half2float(h1)));
        L[i * 2 + 1] = __half2(__float2half_rn(a.z - __half2float(h2)),
                               __float2half_rn(a.w - __half2float(h3)));
    } else if (i < N4_X + N4_WQ) {
        int j = i - N4_X;
        float4 a = ((const float4*)wq)[j];
        __half2* H = (__half2*)g_wqh;
        H[j * 2 + 0] = __half2(__float2half_rn(a.x), __float2half_rn(a.y));
        H[j * 2 + 1] = __half2(__float2half_rn(a.z), __float2half_rn(a.w));
    } else if (i < N4_ALL) {
        int j = i - N4_X - N4_WQ;
        float4 a = ((const float4*)wo)[j];
        __half2* H = (__half2*)g_woh;
        H[j * 2 + 0] = __half2(__float2half_rn(a.x), __float2half_rn(a.y));
        H[j * 2 + 1] = __half2(__float2half_rn(a.z), __float2half_rn(a.w));
    }
}

// ---------------- mma.sync GEMM: C[M,N] = (Ah+Al) @ Bh^T + bias -------------
// 128x128 block, BK=128 (two 64-col subtiles, SW128), 8 warps (64x32 warp
// tile), 2-stage double buffer, ping-pong ldmatrix fragments.
// QKV=true epilogue: cols [0,1024) -> fp32 Q, [1024,2048) -> fp16 K,
// [2048,3072) -> fp16 V.
#define SUB_B   16384
#define OP_B    32768
#define STAGE_B (3 * OP_B)             // Ah, Al, Bh  (96 KB)
#define NCH     (KD / 128)             // 8 chunks

__device__ __forceinline__ uint32_t swz(int row, int u) {
    return (uint32_t)(row * 128 + ((u ^ (row & 7)) << 4));
}

__device__ __forceinline__ void load_stage(
    uint32_t sbase, int s, int chunk, int tm0, int tn0,
    const __half* Ah, const __half* Al, const __half* Bh, int tid)
{
    const __half* srcs[3] = {Ah, Al, Bh};
    uint32_t st = sbase + s * STAGE_B;
#pragma unroll
    for (int i = 0; i < 24; i++) {
        int id  = tid + (i << 8);
        int t   = id >> 11;
        int rem = id & 2047;
        int sub = rem >> 10;
        int rr  = rem & 1023;
        int row = rr >> 3;
        int u   = rr & 7;
        int g0  = (t < 2) ? tm0 : tn0;
        const __half* src = srcs[t] + (size_t)(g0 + row) * KD + chunk * 128 + sub * 64 + u * 8;
        CP_ASYNC16(st + t * OP_B + sub * SUB_B + swz(row, u), src);
    }
    CP_COMMIT();
}

struct Frag {
    uint32_t a_h[4][4], a_l[4][4];
    uint32_t b_h[4][2];
};

__device__ __forceinline__ void load_frags(Frag& f, uint32_t st, int ks,
                                           int wm, int wn, int lane)
{
    const uint32_t sb = st + (uint32_t)((ks >> 2) * SUB_B);
    const int ksl = ks & 3;
    const int ar = lane & 15;
    const int au = ksl * 2 + (lane >> 4);
#pragma unroll
    for (int mt = 0; mt < 4; mt++) {
        uint32_t off = swz(wm + mt * 16 + ar, au);
        ldsm_x4(f.a_h[mt], sb + 0 * OP_B + off);
        ldsm_x4(f.a_l[mt], sb + 1 * OP_B + off);
    }
    const int br = lane & 7;
    const int bu = ksl * 2 + ((lane >> 3) & 1);
    const int bt = (lane >> 4) & 1;
#pragma unroll
    for (int p = 0; p < 2; p++) {
        uint32_t off = swz(wn + (p * 2 + bt) * 8 + br, bu);
        ldsm_x4(&f.b_h[p * 2][0], sb + 2 * OP_B + off);
    }
}

__device__ __forceinline__ void mma_all(float (*acc)[4][4], const Frag& f)
{
#pragma unroll
    for (int mt = 0; mt < 4; mt++)
#pragma unroll
        for (int nt = 0; nt < 4; nt++)
            mma_f16(acc[mt][nt], f.a_h[mt], f.b_h[nt]);
#pragma unroll
    for (int mt = 0; mt < 4; mt++)
#pragma unroll
        for (int nt = 0; nt < 4; nt++)
            mma_f16(acc[mt][nt], f.a_l[mt], f.b_h[nt]);
}

template <bool QKV>
__global__ __launch_bounds__(256, 1)
void gemm_mma(const __half* __restrict__ Ah, const __half* __restrict__ Al,
              const __half* __restrict__ Bh,
              const float* __restrict__ bias, float* __restrict__ C,
              __half* __restrict__ K16, __half* __restrict__ V16, int N)
{
    extern __shared__ __align__(128) char smem[];
    const uint32_t sbase = smem_u32(smem);
    const int tid = threadIdx.x, wid = tid >> 5, lane = tid & 31;
    const int tn0 = blockIdx.x * 128, tm0 = blockIdx.y * 128;
    const int wm = (wid & 1) * 64;
    const int wn = (wid >> 1) * 32;

    float acc[4][4][4];
#pragma unroll
    for (int i = 0; i < 4; i++)
#pragma unroll
        for (int j = 0; j < 4; j++)
#pragma unroll
            for (int k = 0; k < 4; k++) acc[i][j][k] = 0.0f;

    Frag f0, f1;
    load_stage(sbase, 0, 0, tm0, tn0, Ah, Al, Bh, tid);

    for (int c = 0; c < NCH; c++) {
        CP_WAIT(0);
        __syncthreads();
        if (c + 1 < NCH)
            load_stage(sbase, (c + 1) & 1, c + 1, tm0, tn0, Ah, Al, Bh, tid);

        const uint32_t st = sbase + (c & 1) * STAGE_B;
        load_frags(f0, st, 0, wm, wn, lane);
        load_frags(f1, st, 1, wm, wn, lane);
#pragma unroll
        for (int ks = 0; ks < 6; ks += 2) {
            mma_all(acc, f0);
            load_frags(f0, st, ks + 2, wm, wn, lane);
            mma_all(acc, f1);
            load_frags(f1, st, ks + 3, wm, wn, lane);
        }
        mma_all(acc, f0);
        mma_all(acc, f1);
        __syncthreads();
    }

    const int erow = tm0 + wm + (lane >> 2);
#pragma unroll
    for (int mt = 0; mt < 4; mt++) {
#pragma unroll
        for (int nt = 0; nt < 4; nt++) {
            const int gcol = tn0 + wn + (lane & 3) * 2 + nt * 8;  // 0..N-1
            float b0 = bias[gcol], b1 = bias[gcol + 1];
            float v00 = acc[mt][nt][0] + b0, v01 = acc[mt][nt][1] + b1;
            float v10 = acc[mt][nt][2] + b0, v11 = acc[mt][nt][3] + b1;
            const int r0 = erow + mt * 16, r1 = r0 + 8;
            if (!QKV) {
                *(float2*)(C + (size_t)r0 * N + gcol) = make_float2(v00, v01);
                *(float2*)(C + (size_t)r1 * N + gcol) = make_float2(v10, v11);
            } else {
                const int region = gcol >> 10;          // 0=Q,1=K,2=V
                const int lcol = gcol & 1023;
                if (region == 0) {
                    *(float2*)(C + (size_t)r0 * DIM + lcol) = make_float2(v00, v01);
                    *(float2*)(C + (size_t)r1 * DIM + lcol) = make_float2(v10, v11);
                } else {
                    __half* dst = (region == 1) ? K16 : V16;
                    *(__half2*)(dst + (size_t)r0 * DIM + lcol) =
                        __floats2half2_rn(v00, v01);
                    *(__half2*)(dst + (size_t)r1 * DIM + lcol) =
                        __floats2half2_rn(v10, v11);
                }
            }
        }
    }
}

// ---------------- gathered attention: 2-group scheme, fp16 K/V --------------
// Warp = one query. Group g=lane>>4 handles neighbor n=2i+g; sub=lane&15 owns
// dims 4*sub..+3. K/V loaded as fp16 (8B/lane/row), converted to fp32.
// No max-subtraction softmax (scores O(1)); single fused pass.
// Group 0 writes fp16-hi, group 1 writes fp16-lo (split feeding GEMM2).
__global__ __launch_bounds__(512)
void attn_kernel(const int* __restrict__ routes)
{
    const unsigned FULL = 0xffffffffu;
    const int lane = threadIdx.x & 31;
    const int warp = threadIdx.x >> 5;
    const int g    = lane >> 4;
    const int sub  = lane & 15;
    const int bh = blockIdx.x >> 7;                  // 128 blocks per (b,h)
    const int q  = ((blockIdx.x & 127) << 4) | warp;
    const int b  = bh >> 4;
    const int h  = bh & 15;

    const int row0 = b * SS;                         // batch row offset
    const float*  qbase = g_qf  + (size_t)row0 * DIM + h * HD + 4 * sub;
    const __half* kbase = g_k16 + (size_t)row0 * DIM + h * HD + 4 * sub;
    const __half* vbase = g_v16 + (size_t)row0 * DIM + h * HD + 4 * sub;

    const float4 qv = *(const float4*)(qbase + (size_t)q * DIM);

    const int* rt = routes + q * KK;
    const int r_lo = rt[lane];
    const int r_hi = rt[lane + 32];

    float s = 0.0f;
    float o0 = 0.0f, o1 = 0.0f, o2 = 0.0f, o3 = 0.0f;

#pragma unroll
    for (int i = 0; i < 32; i++) {
        int n = 2 * i + g;
        int r = __shfl_sync(FULL, (i < 16) ? r_lo : r_hi, n & 31);
        const size_t roff = (size_t)r * DIM;
        const uint2 kp = *(const uint2*)(kbase + roff);
        const uint2 vp = *(const uint2*)(vbase + roff);
        const float2 k01 = __half22float2(*(const __half2*)&kp.x);
        const float2 k23 = __half22float2(*(const __half2*)&kp.y);
        float p = qv.x * k01.x + qv.y * k01.y + qv.z * k23.x + qv.w * k23.y;
        p += __shfl_xor_sync(FULL, p, 8);
        p += __shfl_xor_sync(FULL, p, 4);
        p += __shfl_xor_sync(FULL, p, 2);
        p += __shfl_xor_sync(FULL, p, 1);
        const float e = __expf(p * 0.125f);
        const float2 v01 = __half22float2(*(const __half2*)&vp.x);
        const float2 v23 = __half22float2(*(const __half2*)&vp.y);
        s += e;
        o0 = fmaf(e, v01.x, o0);
        o1 = fmaf(e, v01.y, o1);
        o2 = fmaf(e, v23.x, o2);
        o3 = fmaf(e, v23.y, o3);
    }

    // combine the two neighbor-halves (lane and lane^16 share `sub`)
    s  += __shfl_xor_sync(FULL, s, 16);
    o0 += __shfl_xor_sync(FULL, o0, 16);
    o1 += __shfl_xor_sync(FULL, o1, 16);
    o2 += __shfl_xor_sync(FULL, o2, 16);
    o3 += __shfl_xor_sync(FULL, o3, 16);
    const float inv = 1.0f / s;
    o0 *= inv; o1 *= inv; o2 *= inv; o3 *= inv;

    // fused fp16 hi/lo split: group 0 -> g_ah, group 1 -> g_al
    const size_t obase = (size_t)(row0 + q) * DIM + h * HD + 4 * sub;
    __half h0 = __float2half_rn(o0), h1 = __float2half_rn(o1);
    __half h2 = __float2half_rn(o2), h3 = __float2half_rn(o3);
    if (g == 0) {
        __half2 p0(h0, h1), p1(h2, h3);
        uint2 pk;
        pk.x = *(uint32_t*)&p0; pk.y = *(uint32_t*)&p1;
        *(uint2*)(g_ah + obase) = pk;
    } else {
        __half2 p0(__float2half_rn(o0 - __half2float(h0)),
                   __float2half_rn(o1 - __half2float(h1)));
        __half2 p1(__float2half_rn(o2 - __half2float(h2)),
                   __float2half_rn(o3 - __half2float(h3)));
        uint2 pk;
        pk.x = *(uint32_t*)&p0; pk.y = *(uint32_t*)&p1;
        *(uint2*)(g_al + obase) = pk;
    }
}

// ---------------------------------------------------------------------------
extern "C" void kernel_launch(void* const* d_in, const int* in_sizes, int n_in,
                              void* d_out, int out_size)
{
    const float* x     = (const float*)d_in[0];
    const float* w_qkv = (const float*)d_in[1];
    const float* b_qkv = (const float*)d_in[2];
    const float* w_out = (const float*)d_in[3];
    const float* b_out = (const float*)d_in[4];
    const int*   routes= (const int*)  d_in[5];
    float* out = (float*)d_out;

    float* qf;
    __half *k16, *v16, *xh, *xl, *wqh, *ah, *al, *woh;
    cudaGetSymbolAddress((void**)&qf,  g_qf);
    cudaGetSymbolAddress((void**)&k16, g_k16);
    cudaGetSymbolAddress((void**)&v16, g_v16);
    cudaGetSymbolAddress((void**)&xh,  g_xh);  cudaGetSymbolAddress((void**)&xl,  g_xl);
    cudaGetSymbolAddress((void**)&wqh, g_wqh);
    cudaGetSymbolAddress((void**)&ah,  g_ah);  cudaGetSymbolAddress((void**)&al,  g_al);
    cudaGetSymbolAddress((void**)&woh, g_woh);

    const int SMEM_TOTAL = 2 * STAGE_B;   // 192 KB
    cudaFuncSetAttribute(gemm_mma<true>,  cudaFuncAttributeMaxDynamicSharedMemorySize, SMEM_TOTAL);
    cudaFuncSetAttribute(gemm_mma<false>, cudaFuncAttributeMaxDynamicSharedMemorySize, SMEM_TOTAL);

    // fused input splits (one launch)
    split_all<<<(N4_ALL + 255) / 256, 256>>>(x, w_qkv, w_out);

    // 1) qkv = x @ w_qkv^T + b_qkv ; epilogue: Q fp32, K/V fp16
    {
        dim3 grid((3 * DIM) / 128, MM / 128);
        gemm_mma<true><<<grid, 256, SMEM_TOTAL>>>(xh, xl, wqh, b_qkv, qf, k16, v16, 3 * DIM);
    }

    // 2) gathered attention (fp16 K/V; writes fp16 hi/lo directly)
    {
        dim3 grid(BB * HH * (SS / 16));
        attn_kernel<<<grid, 512>>>(routes);
    }

    // 3) out = attn @ w_out^T + b_out : [4096, 1024]
    {
        dim3 grid(DIM / 128, MM / 128);
        gemm_mma<false><<<grid, 256, SMEM_TOTAL>>>(ah, al, woh, b_out, out, nullptr, nullptr, DIM);
    }
}

// round 16
// speedup vs baseline: 1.4241x; 1.2369x over previous
#include <cuda_runtime.h>
#include <cuda_fp16.h>
#include <cstdint>

// CantorAttention: B=2, S=2048, DIM=1024, H=16, HD=64, K=64
// GEMM1 (qkv): SINGLE-product fp16 (K/V are fp16-rounded anyway; Q noise
// sub-dominant vs K's fp16 rounding). GEMM2 (out): 2-product fp16 split.
// Attention: 2-group fused pass, fp16 K/V.

#define BB   2
#define SS   2048
#define DIM  1024
#define HH   16
#define HD   64
#define KK   64
#define MM   (BB * SS)        // 4096
#define KD   1024

// ---------------- scratch ---------------------------------------------------
static __device__ float  g_qf[(size_t)MM * DIM];            // Q fp32
static __device__ __half g_k16[(size_t)MM * DIM];           // K fp16
static __device__ __half g_v16[(size_t)MM * DIM];           // V fp16
static __device__ __half g_xh[(size_t)MM * KD];
static __device__ __half g_wqh[(size_t)3 * DIM * KD];
static __device__ __half g_ah[(size_t)MM * KD],  g_al[(size_t)MM * KD];
static __device__ __half g_woh[(size_t)DIM * KD];

// ---------------- helpers ---------------------------------------------------
__device__ __forceinline__ uint32_t smem_u32(const void* p) {
    uint32_t a;
    asm("{ .reg .u64 t; cvta.to.shared.u64 t, %1; cvt.u32.u64 %0, t; }" : "=r"(a) : "l"(p));
    return a;
}
#define CP_ASYNC16(d, s)  asm volatile("cp.async.cg.shared.global [%0], [%1], 16;" :: "r"(d), "l"(s) : "memory")
#define CP_COMMIT()       asm volatile("cp.async.commit_group;" ::: "memory")
#define CP_WAIT(n)        asm volatile("cp.async.wait_group %0;" :: "n"(n) : "memory")

__device__ __forceinline__ void ldsm_x4(uint32_t* r, uint32_t addr) {
    asm volatile("ldmatrix.sync.aligned.m8n8.x4.shared.b16 {%0,%1,%2,%3}, [%4];"
                 : "=r"(r[0]), "=r"(r[1]), "=r"(r[2]), "=r"(r[3]) : "r"(addr));
}
__device__ __forceinline__ void mma_f16(float* d, const uint32_t* a, const uint32_t* b) {
    asm volatile("mma.sync.aligned.m16n8k16.row.col.f32.f16.f16.f32 "
                 "{%0,%1,%2,%3}, {%4,%5,%6,%7}, {%8,%9}, {%0,%1,%2,%3};"
                 : "+f"(d[0]), "+f"(d[1]), "+f"(d[2]), "+f"(d[3])
                 : "r"(a[0]), "r"(a[1]), "r"(a[2]), "r"(a[3]), "r"(b[0]), "r"(b[1]));
}

// ---------------- fused split: x->hi, w_qkv->hi, w_out->hi -------------------
#define N4_X   (MM * KD / 4)
#define N4_WQ  (3 * DIM * KD / 4)
#define N4_WO  (DIM * KD / 4)
#define N4_ALL (N4_X + N4_WQ + N4_WO)

__global__ __launch_bounds__(256)
void split_all(const float* __restrict__ x, const float* __restrict__ wq,
               const float* __restrict__ wo)
{
    int i = blockIdx.x * 256 + threadIdx.x;
    const float* src;
    __half2* dst;
    int j;
    if (i < N4_X)                { src = x;  dst = (__half2*)g_xh;  j = i; }
    else if (i < N4_X + N4_WQ)   { src = wq; dst = (__half2*)g_wqh; j = i - N4_X; }
    else if (i < N4_ALL)         { src = wo; dst = (__half2*)g_woh; j = i - N4_X - N4_WQ; }
    else return;
    float4 a = ((const float4*)src)[j];
    dst[j * 2 + 0] = __half2(__float2half_rn(a.x), __float2half_rn(a.y));
    dst[j * 2 + 1] = __half2(__float2half_rn(a.z), __float2half_rn(a.w));
}

// ---------------- mma.sync GEMM --------------------------------------------
// 128x128 block, BK=128 (two 64-col subtiles, SW128), 8 warps (64x32 warp
// tile), 2-stage double buffer, ping-pong ldmatrix fragments.
// TWOPROD: C = (Ah+Al) @ Bh^T ; else C = Ah @ Bh^T.
// QKV epilogue: cols [0,1024)->fp32 Q, [1024,2048)->fp16 K, [2048,3072)->fp16 V.
#define SUB_B   16384
#define OP_B    32768
#define NCH     (KD / 128)             // 8 chunks

__device__ __forceinline__ uint32_t swz(int row, int u) {
    return (uint32_t)(row * 128 + ((u ^ (row & 7)) << 4));
}

template <int NOP>
__device__ __forceinline__ void load_stage(
    uint32_t sbase, int s, int chunk, int tm0, int tn0,
    const __half* Ah, const __half* Al, const __half* Bh, int tid)
{
    const __half* srcs[3];
    srcs[0] = Ah;
    if (NOP == 3) { srcs[1] = Al; srcs[2] = Bh; }
    else          { srcs[1] = Bh; srcs[2] = Bh; }
    uint32_t st = sbase + s * (NOP * OP_B);
#pragma unroll
    for (int i = 0; i < NOP * 8; i++) {
        int id  = tid + (i << 8);
        int t   = id >> 11;                   // operand
        int rem = id & 2047;
        int sub = rem >> 10;
        int rr  = rem & 1023;
        int row = rr >> 3;
        int u   = rr & 7;
        int g0  = (t < NOP - 1) ? tm0 : tn0;  // last operand is B
        const __half* src = srcs[t] + (size_t)(g0 + row) * KD + chunk * 128 + sub * 64 + u * 8;
        CP_ASYNC16(st + t * OP_B + sub * SUB_B + swz(row, u), src);
    }
    CP_COMMIT();
}

struct Frag {
    uint32_t a_h[4][4], a_l[4][4];
    uint32_t b_h[4][2];
};

template <bool TWOPROD>
__device__ __forceinline__ void load_frags(Frag& f, uint32_t st, int ks,
                                           int wm, int wn, int lane)
{
    const int NOP = TWOPROD ? 3 : 2;
    const uint32_t sb = st + (uint32_t)((ks >> 2) * SUB_B);
    const int ksl = ks & 3;
    const int ar = lane & 15;
    const int au = ksl * 2 + (lane >> 4);
#pragma unroll
    for (int mt = 0; mt < 4; mt++) {
        uint32_t off = swz(wm + mt * 16 + ar, au);
        ldsm_x4(f.a_h[mt], sb + 0 * OP_B + off);
        if (TWOPROD) ldsm_x4(f.a_l[mt], sb + 1 * OP_B + off);
    }
    const int br = lane & 7;
    const int bu = ksl * 2 + ((lane >> 3) & 1);
    const int bt = (lane >> 4) & 1;
#pragma unroll
    for (int p = 0; p < 2; p++) {
        uint32_t off = swz(wn + (p * 2 + bt) * 8 + br, bu);
        ldsm_x4(&f.b_h[p * 2][0], sb + (NOP - 1) * OP_B + off);
    }
}

template <bool TWOPROD>
__device__ __forceinline__ void mma_all(float (*acc)[4][4], const Frag& f)
{
#pragma unroll
    for (int mt = 0; mt < 4; mt++)
#pragma unroll
        for (int nt = 0; nt < 4; nt++)
            mma_f16(acc[mt][nt], f.a_h[mt], f.b_h[nt]);
    if (TWOPROD) {
#pragma unroll
        for (int mt = 0; mt < 4; mt++)
#pragma unroll
            for (int nt = 0; nt < 4; nt++)
                mma_f16(acc[mt][nt], f.a_l[mt], f.b_h[nt]);
    }
}

template <bool QKV, bool TWOPROD>
__global__ __launch_bounds__(256, 1)
void gemm_mma(const __half* __restrict__ Ah, const __half* __restrict__ Al,
              const __half* __restrict__ Bh,
              const float* __restrict__ bias, float* __restrict__ C,
              __half* __restrict__ K16, __half* __restrict__ V16, int N)
{
    constexpr int NOP = TWOPROD ? 3 : 2;
    constexpr int STG = NOP * OP_B;
    extern __shared__ __align__(128) char smem[];
    const uint32_t sbase = smem_u32(smem);
    const int tid = threadIdx.x, wid = tid >> 5, lane = tid & 31;
    const int tn0 = blockIdx.x * 128, tm0 = blockIdx.y * 128;
    const int wm = (wid & 1) * 64;
    const int wn = (wid >> 1) * 32;

    float acc[4][4][4];
#pragma unroll
    for (int i = 0; i < 4; i++)
#pragma unroll
        for (int j = 0; j < 4; j++)
#pragma unroll
            for (int k = 0; k < 4; k++) acc[i][j][k] = 0.0f;

    Frag f0, f1;
    load_stage<NOP>(sbase, 0, 0, tm0, tn0, Ah, Al, Bh, tid);

    for (int c = 0; c < NCH; c++) {
        CP_WAIT(0);
        __syncthreads();
        if (c + 1 < NCH)
            load_stage<NOP>(sbase, (c + 1) & 1, c + 1, tm0, tn0, Ah, Al, Bh, tid);

        const uint32_t st = sbase + (c & 1) * STG;
        load_frags<TWOPROD>(f0, st, 0, wm, wn, lane);
        load_frags<TWOPROD>(f1, st, 1, wm, wn, lane);
#pragma unroll
        for (int ks = 0; ks < 6; ks += 2) {
            mma_all<TWOPROD>(acc, f0);
            load_frags<TWOPROD>(f0, st, ks + 2, wm, wn, lane);
            mma_all<TWOPROD>(acc, f1);
            load_frags<TWOPROD>(f1, st, ks + 3, wm, wn, lane);
        }
        mma_all<TWOPROD>(acc, f0);
        mma_all<TWOPROD>(acc, f1);
        __syncthreads();
    }

    const int erow = tm0 + wm + (lane >> 2);
#pragma unroll
    for (int mt = 0; mt < 4; mt++) {
#pragma unroll
        for (int nt = 0; nt < 4; nt++) {
            const int gcol = tn0 + wn + (lane & 3) * 2 + nt * 8;
            float b0 = bias[gcol], b1 = bias[gcol + 1];
            float v00 = acc[mt][nt][0] + b0, v01 = acc[mt][nt][1] + b1;
            float v10 = acc[mt][nt][2] + b0, v11 = acc[mt][nt][3] + b1;
            const int r0 = erow + mt * 16, r1 = r0 + 8;
            if (!QKV) {
                *(float2*)(C + (size_t)r0 * N + gcol) = make_float2(v00, v01);
                *(float2*)(C + (size_t)r1 * N + gcol) = make_float2(v10, v11);
            } else {
                const int region = gcol >> 10;          // 0=Q,1=K,2=V
                const int lcol = gcol & 1023;
                if (region == 0) {
                    *(float2*)(C + (size_t)r0 * DIM + lcol) = make_float2(v00, v01);
                    *(float2*)(C + (size_t)r1 * DIM + lcol) = make_float2(v10, v11);
                } else {
                    __half* dst = (region == 1) ? K16 : V16;
                    *(__half2*)(dst + (size_t)r0 * DIM + lcol) =
                        __floats2half2_rn(v00, v01);
                    *(__half2*)(dst + (size_t)r1 * DIM + lcol) =
                        __floats2half2_rn(v10, v11);
                }
            }
        }
    }
}

// ---------------- gathered attention: 2-group scheme, fp16 K/V --------------
__global__ __launch_bounds__(512)
void attn_kernel(const int* __restrict__ routes)
{
    const unsigned FULL = 0xffffffffu;
    const int lane = threadIdx.x & 31;
    const int warp = threadIdx.x >> 5;
    const int g    = lane >> 4;
    const int sub  = lane & 15;
    const int bh = blockIdx.x >> 7;                  // 128 blocks per (b,h)
    const int q  = ((blockIdx.x & 127) << 4) | warp;
    const int b  = bh >> 4;
    const int h  = bh & 15;

    const int row0 = b * SS;
    const float*  qbase = g_qf  + (size_t)row0 * DIM + h * HD + 4 * sub;
    const __half* kbase = g_k16 + (size_t)row0 * DIM + h * HD + 4 * sub;
    const __half* vbase = g_v16 + (size_t)row0 * DIM + h * HD + 4 * sub;

    const float4 qv = *(const float4*)(qbase + (size_t)q * DIM);

    const int* rt = routes + q * KK;
    const int r_lo = rt[lane];
    const int r_hi = rt[lane + 32];

    float s = 0.0f;
    float o0 = 0.0f, o1 = 0.0f, o2 = 0.0f, o3 = 0.0f;

#pragma unroll
    for (int i = 0; i < 32; i++) {
        int n = 2 * i + g;
        int r = __shfl_sync(FULL, (i < 16) ? r_lo : r_hi, n & 31);
        const size_t roff = (size_t)r * DIM;
        const uint2 kp = *(const uint2*)(kbase + roff);
        const uint2 vp = *(const uint2*)(vbase + roff);
        const float2 k01 = __half22float2(*(const __half2*)&kp.x);
        const float2 k23 = __half22float2(*(const __half2*)&kp.y);
        float p = qv.x * k01.x + qv.y * k01.y + qv.z * k23.x + qv.w * k23.y;
        p += __shfl_xor_sync(FULL, p, 8);
        p += __shfl_xor_sync(FULL, p, 4);
        p += __shfl_xor_sync(FULL, p, 2);
        p += __shfl_xor_sync(FULL, p, 1);
        const float e = __expf(p * 0.125f);
        const float2 v01 = __half22float2(*(const __half2*)&vp.x);
        const float2 v23 = __half22float2(*(const __half2*)&vp.y);
        s += e;
        o0 = fmaf(e, v01.x, o0);
        o1 = fmaf(e, v01.y, o1);
        o2 = fmaf(e, v23.x, o2);
        o3 = fmaf(e, v23.y, o3);
    }

    s  += __shfl_xor_sync(FULL, s, 16);
    o0 += __shfl_xor_sync(FULL, o0, 16);
    o1 += __shfl_xor_sync(FULL, o1, 16);
    o2 += __shfl_xor_sync(FULL, o2, 16);
    o3 += __shfl_xor_sync(FULL, o3, 16);
    const float inv = 1.0f / s;
    o0 *= inv; o1 *= inv; o2 *= inv; o3 *= inv;

    // fused fp16 hi/lo split: group 0 -> g_ah, group 1 -> g_al
    const size_t obase = (size_t)(row0 + q) * DIM + h * HD + 4 * sub;
    __half h0 = __float2half_rn(o0), h1 = __float2half_rn(o1);
    __half h2 = __float2half_rn(o2), h3 = __float2half_rn(o3);
    if (g == 0) {
        __half2 p0(h0, h1), p1(h2, h3);
        uint2 pk;
        pk.x = *(uint32_t*)&p0; pk.y = *(uint32_t*)&p1;
        *(uint2*)(g_ah + obase) = pk;
    } else {
        __half2 p0(__float2half_rn(o0 - __half2float(h0)),
                   __float2half_rn(o1 - __half2float(h1)));
        __half2 p1(__float2half_rn(o2 - __half2float(h2)),
                   __float2half_rn(o3 - __half2float(h3)));
        uint2 pk;
        pk.x = *(uint32_t*)&p0; pk.y = *(uint32_t*)&p1;
        *(uint2*)(g_al + obase) = pk;
    }
}

// ---------------------------------------------------------------------------
extern "C" void kernel_launch(void* const* d_in, const int* in_sizes, int n_in,
                              void* d_out, int out_size)
{
    const float* x     = (const float*)d_in[0];
    const float* w_qkv = (const float*)d_in[1];
    const float* b_qkv = (const float*)d_in[2];
    const float* w_out = (const float*)d_in[3];
    const float* b_out = (const float*)d_in[4];
    const int*   routes= (const int*)  d_in[5];
    float* out = (float*)d_out;

    float* qf;
    __half *k16, *v16, *xh, *wqh, *ah, *al, *woh;
    cudaGetSymbolAddress((void**)&qf,  g_qf);
    cudaGetSymbolAddress((void**)&k16, g_k16);
    cudaGetSymbolAddress((void**)&v16, g_v16);
    cudaGetSymbolAddress((void**)&xh,  g_xh);
    cudaGetSymbolAddress((void**)&wqh, g_wqh);
    cudaGetSymbolAddress((void**)&ah,  g_ah);  cudaGetSymbolAddress((void**)&al,  g_al);
    cudaGetSymbolAddress((void**)&woh, g_woh);

    const int SMEM1 = 2 * 2 * OP_B;   // 128 KB (single-product: Ah, Bh)
    const int SMEM2 = 2 * 3 * OP_B;   // 192 KB (2-product: Ah, Al, Bh)
    cudaFuncSetAttribute(gemm_mma<true, false>, cudaFuncAttributeMaxDynamicSharedMemorySize, SMEM1);
    cudaFuncSetAttribute(gemm_mma<false, true>, cudaFuncAttributeMaxDynamicSharedMemorySize, SMEM2);

    // fused input conversions (one launch)
    split_all<<<(N4_ALL + 255) / 256, 256>>>(x, w_qkv, w_out);

    // 1) qkv = x @ w_qkv^T + b_qkv ; single product, epilogue Q fp32 / K,V fp16
    {
        dim3 grid((3 * DIM) / 128, MM / 128);
        gemm_mma<true, false><<<grid, 256, SMEM1>>>(xh, nullptr, wqh, b_qkv, qf, k16, v16, 3 * DIM);
    }

    // 2) gathered attention (fp16 K/V; writes fp16 hi/lo directly)
    {
        dim3 grid(BB * HH * (SS / 16));
        attn_kernel<<<grid, 512>>>(routes);
    }

    // 3) out = attn @ w_out^T + b_out ; 2-product
    {
        dim3 grid(DIM / 128, MM / 128);
        gemm_mma<false, true><<<grid, 256, SMEM2>>>(ah, al, woh, b_out, out, nullptr, nullptr, DIM);
    }
}

// round 17
// speedup vs baseline: 1.5521x; 1.0899x over previous
#include <cuda_runtime.h>
#include <cuda_fp16.h>
#include <cstdint>

// CantorAttention: B=2, S=2048, DIM=1024, H=16, HD=64, K=64
// Both GEMMs single-product fp16 (error budget calibrated: ~6.9e-4 vs 1e-3).
// Attention: 2-group fused pass, fp16 K/V, writes fp16 attn directly.

#define BB   2
#define SS   2048
#define DIM  1024
#define HH   16
#define HD   64
#define KK   64
#define MM   (BB * SS)        // 4096
#define KD   1024

// ---------------- scratch ---------------------------------------------------
static __device__ float  g_qf[(size_t)MM * DIM];            // Q fp32
static __device__ __half g_k16[(size_t)MM * DIM];           // K fp16
static __device__ __half g_v16[(size_t)MM * DIM];           // V fp16
static __device__ __half g_xh[(size_t)MM * KD];
static __device__ __half g_wqh[(size_t)3 * DIM * KD];
static __device__ __half g_ah[(size_t)MM * KD];             // attn fp16
static __device__ __half g_woh[(size_t)DIM * KD];

// ---------------- helpers ---------------------------------------------------
__device__ __forceinline__ uint32_t smem_u32(const void* p) {
    uint32_t a;
    asm("{ .reg .u64 t; cvta.to.shared.u64 t, %1; cvt.u32.u64 %0, t; }" : "=r"(a) : "l"(p));
    return a;
}
#define CP_ASYNC16(d, s)  asm volatile("cp.async.cg.shared.global [%0], [%1], 16;" :: "r"(d), "l"(s) : "memory")
#define CP_COMMIT()       asm volatile("cp.async.commit_group;" ::: "memory")
#define CP_WAIT(n)        asm volatile("cp.async.wait_group %0;" :: "n"(n) : "memory")

__device__ __forceinline__ void ldsm_x4(uint32_t* r, uint32_t addr) {
    asm volatile("ldmatrix.sync.aligned.m8n8.x4.shared.b16 {%0,%1,%2,%3}, [%4];"
                 : "=r"(r[0]), "=r"(r[1]), "=r"(r[2]), "=r"(r[3]) : "r"(addr));
}
__device__ __forceinline__ void mma_f16(float* d, const uint32_t* a, const uint32_t* b) {
    asm volatile("mma.sync.aligned.m16n8k16.row.col.f32.f16.f16.f32 "
                 "{%0,%1,%2,%3}, {%4,%5,%6,%7}, {%8,%9}, {%0,%1,%2,%3};"
                 : "+f"(d[0]), "+f"(d[1]), "+f"(d[2]), "+f"(d[3])
                 : "r"(a[0]), "r"(a[1]), "r"(a[2]), "r"(a[3]), "r"(b[0]), "r"(b[1]));
}

// ---------------- fused conversion: x, w_qkv, w_out -> fp16 ------------------
#define N4_X   (MM * KD / 4)
#define N4_WQ  (3 * DIM * KD / 4)
#define N4_WO  (DIM * KD / 4)
#define N4_ALL (N4_X + N4_WQ + N4_WO)

__global__ __launch_bounds__(256)
void split_all(const float* __restrict__ x, const float* __restrict__ wq,
               const float* __restrict__ wo)
{
    int i = blockIdx.x * 256 + threadIdx.x;
    const float* src;
    __half2* dst;
    int j;
    if (i < N4_X)                { src = x;  dst = (__half2*)g_xh;  j = i; }
    else if (i < N4_X + N4_WQ)   { src = wq; dst = (__half2*)g_wqh; j = i - N4_X; }
    else if (i < N4_ALL)         { src = wo; dst = (__half2*)g_woh; j = i - N4_X - N4_WQ; }
    else return;
    float4 a = ((const float4*)src)[j];
    dst[j * 2 + 0] = __half2(__float2half_rn(a.x), __float2half_rn(a.y));
    dst[j * 2 + 1] = __half2(__float2half_rn(a.z), __float2half_rn(a.w));
}

// ---------------- mma.sync GEMM: C[M,N] = Ah @ Bh^T + bias ------------------
// 128x128 block, BK=128 (two 64-col subtiles, SW128), 8 warps (64x32 warp
// tile), 2-stage double buffer, ping-pong ldmatrix fragments.
// QKV epilogue: cols [0,1024)->fp32 Q, [1024,2048)->fp16 K, [2048,3072)->fp16 V.
#define SUB_B   16384
#define OP_B    32768
#define STG_B   (2 * OP_B)             // Ah, Bh  (64 KB)
#define NCH     (KD / 128)             // 8 chunks

__device__ __forceinline__ uint32_t swz(int row, int u) {
    return (uint32_t)(row * 128 + ((u ^ (row & 7)) << 4));
}

__device__ __forceinline__ void load_stage(
    uint32_t sbase, int s, int chunk, int tm0, int tn0,
    const __half* Ah, const __half* Bh, int tid)
{
    const __half* srcs[2] = {Ah, Bh};
    uint32_t st = sbase + s * STG_B;
#pragma unroll
    for (int i = 0; i < 16; i++) {
        int id  = tid + (i << 8);
        int t   = id >> 11;                // operand 0..1
        int rem = id & 2047;
        int sub = rem >> 10;
        int rr  = rem & 1023;
        int row = rr >> 3;
        int u   = rr & 7;
        int g0  = (t == 0) ? tm0 : tn0;
        const __half* src = srcs[t] + (size_t)(g0 + row) * KD + chunk * 128 + sub * 64 + u * 8;
        CP_ASYNC16(st + t * OP_B + sub * SUB_B + swz(row, u), src);
    }
    CP_COMMIT();
}

struct Frag {
    uint32_t a_h[4][4];
    uint32_t b_h[4][2];
};

__device__ __forceinline__ void load_frags(Frag& f, uint32_t st, int ks,
                                           int wm, int wn, int lane)
{
    const uint32_t sb = st + (uint32_t)((ks >> 2) * SUB_B);
    const int ksl = ks & 3;
    const int ar = lane & 15;
    const int au = ksl * 2 + (lane >> 4);
#pragma unroll
    for (int mt = 0; mt < 4; mt++) {
        uint32_t off = swz(wm + mt * 16 + ar, au);
        ldsm_x4(f.a_h[mt], sb + 0 * OP_B + off);
    }
    const int br = lane & 7;
    const int bu = ksl * 2 + ((lane >> 3) & 1);
    const int bt = (lane >> 4) & 1;
#pragma unroll
    for (int p = 0; p < 2; p++) {
        uint32_t off = swz(wn + (p * 2 + bt) * 8 + br, bu);
        ldsm_x4(&f.b_h[p * 2][0], sb + 1 * OP_B + off);
    }
}

__device__ __forceinline__ void mma_all(float (*acc)[4][4], const Frag& f)
{
#pragma unroll
    for (int mt = 0; mt < 4; mt++)
#pragma unroll
        for (int nt = 0; nt < 4; nt++)
            mma_f16(acc[mt][nt], f.a_h[mt], f.b_h[nt]);
}

template <bool QKV>
__global__ __launch_bounds__(256, 1)
void gemm_mma(const __half* __restrict__ Ah, const __half* __restrict__ Bh,
              const float* __restrict__ bias, float* __restrict__ C,
              __half* __restrict__ K16, __half* __restrict__ V16, int N)
{
    extern __shared__ __align__(128) char smem[];
    const uint32_t sbase = smem_u32(smem);
    const int tid = threadIdx.x, wid = tid >> 5, lane = tid & 31;
    const int tn0 = blockIdx.x * 128, tm0 = blockIdx.y * 128;
    const int wm = (wid & 1) * 64;
    const int wn = (wid >> 1) * 32;

    float acc[4][4][4];
#pragma unroll
    for (int i = 0; i < 4; i++)
#pragma unroll
        for (int j = 0; j < 4; j++)
#pragma unroll
            for (int k = 0; k < 4; k++) acc[i][j][k] = 0.0f;

    Frag f0, f1;
    load_stage(sbase, 0, 0, tm0, tn0, Ah, Bh, tid);

    for (int c = 0; c < NCH; c++) {
        CP_WAIT(0);
        __syncthreads();
        if (c + 1 < NCH)
            load_stage(sbase, (c + 1) & 1, c + 1, tm0, tn0, Ah, Bh, tid);

        const uint32_t st = sbase + (c & 1) * STG_B;
        load_frags(f0, st, 0, wm, wn, lane);
        load_frags(f1, st, 1, wm, wn, lane);
#pragma unroll
        for (int ks = 0; ks < 6; ks += 2) {
            mma_all(acc, f0);
            load_frags(f0, st, ks + 2, wm, wn, lane);
            mma_all(acc, f1);
            load_frags(f1, st, ks + 3, wm, wn, lane);
        }
        mma_all(acc, f0);
        mma_all(acc, f1);
        __syncthreads();
    }

    const int erow = tm0 + wm + (lane >> 2);
#pragma unroll
    for (int mt = 0; mt < 4; mt++) {
#pragma unroll
        for (int nt = 0; nt < 4; nt++) {
            const int gcol = tn0 + wn + (lane & 3) * 2 + nt * 8;
            float b0 = bias[gcol], b1 = bias[gcol + 1];
            float v00 = acc[mt][nt][0] + b0, v01 = acc[mt][nt][1] + b1;
            float v10 = acc[mt][nt][2] + b0, v11 = acc[mt][nt][3] + b1;
            const int r0 = erow + mt * 16, r1 = r0 + 8;
            if (!QKV) {
                *(float2*)(C + (size_t)r0 * N + gcol) = make_float2(v00, v01);
                *(float2*)(C + (size_t)r1 * N + gcol) = make_float2(v10, v11);
            } else {
                const int region = gcol >> 10;          // 0=Q,1=K,2=V
                const int lcol = gcol & 1023;
                if (region == 0) {
                    *(float2*)(C + (size_t)r0 * DIM + lcol) = make_float2(v00, v01);
                    *(float2*)(C + (size_t)r1 * DIM + lcol) = make_float2(v10, v11);
                } else {
                    __half* dst = (region == 1) ? K16 : V16;
                    *(__half2*)(dst + (size_t)r0 * DIM + lcol) =
                        __floats2half2_rn(v00, v01);
                    *(__half2*)(dst + (size_t)r1 * DIM + lcol) =
                        __floats2half2_rn(v10, v11);
                }
            }
        }
    }
}

// ---------------- gathered attention: 2-group scheme, fp16 K/V --------------
// Warp = one query. Group g=lane>>4 handles neighbor n=2i+g; sub=lane&15 owns
// dims 4*sub..+3. Output written once (group 0) as fp16 for GEMM2.
__global__ __launch_bounds__(512)
void attn_kernel(const int* __restrict__ routes)
{
    const unsigned FULL = 0xffffffffu;
    const int lane = threadIdx.x & 31;
    const int warp = threadIdx.x >> 5;
    const int g    = lane >> 4;
    const int sub  = lane & 15;
    const int bh = blockIdx.x >> 7;                  // 128 blocks per (b,h)
    const int q  = ((blockIdx.x & 127) << 4) | warp;
    const int b  = bh >> 4;
    const int h  = bh & 15;

    const int row0 = b * SS;
    const float*  qbase = g_qf  + (size_t)row0 * DIM + h * HD + 4 * sub;
    const __half* kbase = g_k16 + (size_t)row0 * DIM + h * HD + 4 * sub;
    const __half* vbase = g_v16 + (size_t)row0 * DIM + h * HD + 4 * sub;

    const float4 qv = *(const float4*)(qbase + (size_t)q * DIM);

    const int* rt = routes + q * KK;
    const int r_lo = rt[lane];
    const int r_hi = rt[lane + 32];

    float s = 0.0f;
    float o0 = 0.0f, o1 = 0.0f, o2 = 0.0f, o3 = 0.0f;

#pragma unroll
    for (int i = 0; i < 32; i++) {
        int n = 2 * i + g;
        int r = __shfl_sync(FULL, (i < 16) ? r_lo : r_hi, n & 31);
        const size_t roff = (size_t)r * DIM;
        const uint2 kp = *(const uint2*)(kbase + roff);
        const uint2 vp = *(const uint2*)(vbase + roff);
        const float2 k01 = __half22float2(*(const __half2*)&kp.x);
        const float2 k23 = __half22float2(*(const __half2*)&kp.y);
        float p = qv.x * k01.x + qv.y * k01.y + qv.z * k23.x + qv.w * k23.y;
        p += __shfl_xor_sync(FULL, p, 8);
        p += __shfl_xor_sync(FULL, p, 4);
        p += __shfl_xor_sync(FULL, p, 2);
        p += __shfl_xor_sync(FULL, p, 1);
        const float e = __expf(p * 0.125f);
        const float2 v01 = __half22float2(*(const __half2*)&vp.x);
        const float2 v23 = __half22float2(*(const __half2*)&vp.y);
        s += e;
        o0 = fmaf(e, v01.x, o0);
        o1 = fmaf(e, v01.y, o1);
        o2 = fmaf(e, v23.x, o2);
        o3 = fmaf(e, v23.y, o3);
    }

    s  += __shfl_xor_sync(FULL, s, 16);
    o0 += __shfl_xor_sync(FULL, o0, 16);
    o1 += __shfl_xor_sync(FULL, o1, 16);
    o2 += __shfl_xor_sync(FULL, o2, 16);
    o3 += __shfl_xor_sync(FULL, o3, 16);
    const float inv = 1.0f / s;

    if (g == 0) {
        const size_t obase = (size_t)(row0 + q) * DIM + h * HD + 4 * sub;
        __half2 p0 = __floats2half2_rn(o0 * inv, o1 * inv);
        __half2 p1 = __floats2half2_rn(o2 * inv, o3 * inv);
        uint2 pk;
        pk.x = *(uint32_t*)&p0; pk.y = *(uint32_t*)&p1;
        *(uint2*)(g_ah + obase) = pk;
    }
}

// ---------------------------------------------------------------------------
extern "C" void kernel_launch(void* const* d_in, const int* in_sizes, int n_in,
                              void* d_out, int out_size)
{
    const float* x     = (const float*)d_in[0];
    const float* w_qkv = (const float*)d_in[1];
    const float* b_qkv = (const float*)d_in[2];
    const float* w_out = (const float*)d_in[3];
    const float* b_out = (const float*)d_in[4];
    const int*   routes= (const int*)  d_in[5];
    float* out = (float*)d_out;

    float* qf;
    __half *k16, *v16, *xh, *wqh, *ah, *woh;
    cudaGetSymbolAddress((void**)&qf,  g_qf);
    cudaGetSymbolAddress((void**)&k16, g_k16);
    cudaGetSymbolAddress((void**)&v16, g_v16);
    cudaGetSymbolAddress((void**)&xh,  g_xh);
    cudaGetSymbolAddress((void**)&wqh, g_wqh);
    cudaGetSymbolAddress((void**)&ah,  g_ah);
    cudaGetSymbolAddress((void**)&woh, g_woh);

    const int SMEM = 2 * STG_B;   // 128 KB
    cudaFuncSetAttribute(gemm_mma<true>,  cudaFuncAttributeMaxDynamicSharedMemorySize, SMEM);
    cudaFuncSetAttribute(gemm_mma<false>, cudaFuncAttributeMaxDynamicSharedMemorySize, SMEM);

    // fused input conversions (one launch)
    split_all<<<(N4_ALL + 255) / 256, 256>>>(x, w_qkv, w_out);

    // 1) qkv = x @ w_qkv^T + b_qkv ; epilogue Q fp32 / K,V fp16
    {
        dim3 grid((3 * DIM) / 128, MM / 128);
        gemm_mma<true><<<grid, 256, SMEM>>>(xh, wqh, b_qkv, qf, k16, v16, 3 * DIM);
    }

    // 2) gathered attention (fp16 K/V; writes fp16 attn)
    {
        dim3 grid(BB * HH * (SS / 16));
        attn_kernel<<<grid, 512>>>(routes);
    }

    // 3) out = attn @ w_out^T + b_out
    {
        dim3 grid(DIM / 128, MM / 128);
        gemm_mma<false><<<grid, 256, SMEM>>>(ah, woh, b_out, out, nullptr, nullptr, DIM);
    }
}